// round 8
// baseline (speedup 1.0000x reference)
#include <cuda_runtime.h>
#include <cstdint>
#include <cstddef>

#define NS 512
#define NB 1024
#define NT 64
#define QSTRIDE 68   // 32 u64 (rows 0-31) + 2 pad + 32 u64 (rows 32-63) + 2 pad

__device__ float g_partial[NB];
__device__ unsigned int g_ctr = 0;

typedef unsigned long long u64;

__device__ __forceinline__ u64 pack2(float lo, float hi) {
    u64 r; asm("mov.b64 %0, {%1, %2};" : "=l"(r) : "f"(lo), "f"(hi)); return r;
}
__device__ __forceinline__ void unpack2(u64 v, float& lo, float& hi) {
    asm("mov.b64 {%0, %1}, %2;" : "=f"(lo), "=f"(hi) : "l"(v));
}
__device__ __forceinline__ void fma2(u64& acc, u64 a, u64 b) {
    asm("fma.rn.f32x2 %0, %1, %2, %0;" : "+l"(acc) : "l"(a), "l"(b));
}
__device__ __forceinline__ u64 add2(u64 a, u64 b) {
    u64 r; asm("add.rn.f32x2 %0, %1, %2;" : "=l"(r) : "l"(a), "l"(b)); return r;
}
__device__ __forceinline__ u64 mul2(u64 a, u64 b) {
    u64 r; asm("mul.rn.f32x2 %0, %1, %2;" : "=l"(r) : "l"(a), "l"(b)); return r;
}
__device__ __forceinline__ float frcp(float x) {
    float r; asm("rcp.approx.f32 %0, %1;" : "=f"(r) : "f"(x)); return r;
}
__device__ __forceinline__ u64 shflx16_u64(u64 v) {
    unsigned lo = (unsigned)v, hi = (unsigned)(v >> 32);
    lo = __shfl_xor_sync(0xffffffffu, lo, 16);
    hi = __shfl_xor_sync(0xffffffffu, hi, 16);
    return ((u64)hi << 32) | lo;
}
__device__ __forceinline__ void sts128(u64* p, float a, float b, float c, float d) {
    asm volatile("st.shared.v4.f32 [%0], {%1, %2, %3, %4};"
                 :: "l"(p), "f"(a), "f"(b), "f"(c), "f"(d) : "memory");
}

__device__ __forceinline__ float gold_score(const float* __restrict__ em,
                                            const float* __restrict__ trans,
                                            const float* __restrict__ start_t,
                                            const float* __restrict__ end_t,
                                            const int* __restrict__ tags,
                                            const int* __restrict__ mask,
                                            int b, int lane) {
    float sc = 0.f;
    int msum = 0;
#pragma unroll
    for (int k = 0; k < 16; k++) {
        int s = 1 + lane + (k << 5);
        if (s < NS) {
            int tp = tags[(s - 1) * NB + b];
            int tc = tags[s * NB + b];
            int mv = mask[s * NB + b];
            float term = trans[tp * NT + tc] + em[((size_t)s * NB + b) * NT + tc];
            sc += term * (float)mv;
            msum += mv;
        }
    }
#pragma unroll
    for (int off = 16; off; off >>= 1) {
        sc   += __shfl_xor_sync(0xffffffffu, sc, off);
        msum += __shfl_xor_sync(0xffffffffu, msum, off);
    }
    int t0 = tags[b];
    sc += start_t[t0] + em[(size_t)b * NT + t0];
    int seq_end = mask[b] + msum - 1;
    int lt = tags[(size_t)seq_end * NB + b];
    sc += end_t[lt];
    return sc;
}

#define NOCL(v) (v)
#define CLV(v)  (((v) < NS - 1) ? (v) : (NS - 1))

__global__ void __launch_bounds__(32)
crf_kernel(const float* __restrict__ em,
           const float* __restrict__ trans,
           const float* __restrict__ start_t,
           const float* __restrict__ end_t,
           const int* __restrict__ tags,
           const int* __restrict__ mask,
           float* __restrict__ out) {
    __shared__ __align__(16) u64 qsm[2][2][QSTRIDE];   // [chain][parity][..]

    const int lane = threadIdx.x;          // one warp, two chains
    const int c    = lane & 15;            // owns cols 4c..4c+3
    const int h    = lane >> 4;            // row half
    const int bA   = blockIdx.x * 2;
    const int bB   = bA + 1;
    const size_t SSTR = (size_t)NB * NT;

    // ---------------- numerators (prologue) ----------------
    float scA = gold_score(em, trans, start_t, end_t, tags, mask, bA, lane);
    float scB = gold_score(em, trans, start_t, end_t, tags, mask, bB, lane);

    // ---------------- E = exp(trans): my 32 rows x my 4 cols (shared by both chains) ----
    u64 EA[32], EB[32];
#pragma unroll
    for (int i = 0; i < 32; i++) {
        float4 t4 = *reinterpret_cast<const float4*>(trans + (32 * h + i) * NT + 4 * c);
        EA[i] = pack2(__expf(t4.x), __expf(t4.y));
        EB[i] = pack2(__expf(t4.z), __expf(t4.w));
    }

    const float* emj4A = em + (size_t)bA * NT + 4 * c;
    const float* emj4B = em + (size_t)bB * NT + 4 * c;
    const int sidx = 4 * c + ((c >= 8) ? 2 : 0);

    // ---------------- per-chain recursion state ----------------
    u64 y01A, y23A, eem01A, eem23A;
    u64 y01B, y23B, eem01B, eem23B;
    float4 pfEA, pfOA, pfEB, pfOB;
    float rcurA = 1.f, lpendA = 0.f, MtotA = 0.f;
    float rcurB = 1.f, lpendB = 0.f, MtotB = 0.f;
    int mkSA, mkS1A, mkSB, mkS1B;

#define CRF_INIT(X, IDX)                                                         \
    {                                                                            \
        float4 e0 = *reinterpret_cast<const float4*>(emj4##X);                   \
        float4 s4 = *reinterpret_cast<const float4*>(start_t + 4 * c);           \
        y01##X = pack2(__expf(s4.x + e0.x), __expf(s4.y + e0.y));                \
        y23##X = pack2(__expf(s4.z + e0.z), __expf(s4.w + e0.w));                \
        float y0, y1, y2, y3;                                                    \
        unpack2(y01##X, y0, y1); unpack2(y23##X, y2, y3);                        \
        if (h == 0) {                                                            \
            sts128(qsm[IDX][1] + sidx,     y0, y0, y1, y1);                      \
            sts128(qsm[IDX][1] + sidx + 2, y2, y2, y3, y3);                      \
        }                                                                        \
        float4 t1 = *reinterpret_cast<const float4*>(emj4##X + 1 * SSTR);        \
        eem01##X = pack2(__expf(t1.x), __expf(t1.y));                            \
        eem23##X = pack2(__expf(t1.z), __expf(t1.w));                            \
        pfE##X = *reinterpret_cast<const float4*>(emj4##X + 2 * SSTR);           \
        pfO##X = *reinterpret_cast<const float4*>(emj4##X + 3 * SSTR);           \
        mkS##X  = mask[1 * NB + b##X];                                           \
        mkS1##X = mask[2 * NB + b##X];                                           \
    }

    CRF_INIT(A, 0)
    CRF_INIT(B, 1)
    __syncwarp();

#define CRF_STEP(X, IDX, P, S, PFN, CL)                                          \
    {                                                                            \
        const u64* qh = qsm[IDX][P] + h * 34;                                    \
        u64 A0 = 0, A1 = 0, A2 = 0, A3 = 0;                                      \
        u64 B0 = 0, B1 = 0, B2 = 0, B3 = 0;                                      \
        _Pragma("unroll")                                                        \
        for (int i = 0; i < 32; i += 4) {                                        \
            ulonglong2 q0 = *reinterpret_cast<const ulonglong2*>(qh + i);        \
            ulonglong2 q1 = *reinterpret_cast<const ulonglong2*>(qh + i + 2);    \
            fma2(A0, q0.x, EA[i]);     fma2(B0, q0.x, EB[i]);                    \
            fma2(A1, q0.y, EA[i + 1]); fma2(B1, q0.y, EB[i + 1]);                \
            fma2(A2, q1.x, EA[i + 2]); fma2(B2, q1.x, EB[i + 2]);                \
            fma2(A3, q1.y, EA[i + 3]); fma2(B3, q1.y, EB[i + 3]);                \
        }                                                                        \
        u64 S01 = add2(add2(A0, A1), add2(A2, A3));                              \
        u64 S23 = add2(add2(B0, B1), add2(B2, B3));                              \
        S01 = add2(S01, shflx16_u64(S01));                                       \
        S23 = add2(S23, shflx16_u64(S23));                                       \
        float alo, ahi; unpack2(S01, alo, ahi);                                  \
        float a0raw = __shfl_sync(0xffffffffu, alo, 0);                          \
        u64 rp = pack2(rcur##X, rcur##X);                                        \
        u64 c01 = mul2(mul2(S01, rp), eem01##X);                                 \
        u64 c23 = mul2(mul2(S23, rp), eem23##X);                                 \
        if (mkS##X) { y01##X = c01; y23##X = c23; }                              \
        float y0, y1, y2, y3;                                                    \
        unpack2(y01##X, y0, y1); unpack2(y23##X, y2, y3);                        \
        if (h == 0) {                                                            \
            sts128(qsm[IDX][(P) ^ 1] + sidx,     y0, y0, y1, y1);                \
            sts128(qsm[IDX][(P) ^ 1] + sidx + 2, y2, y2, y3, y3);                \
        }                                                                        \
        float u0n = a0raw * rcur##X;                                             \
        if (mkS##X) { Mtot##X += lpend##X; lpend##X = __logf(u0n);               \
                      rcur##X = frcp(u0n); }                                     \
        mkS##X = mkS1##X;                                                        \
        mkS1##X = mask[CL((S) + 2) * NB + b##X];                                 \
        eem01##X = pack2(__expf(PFN.x), __expf(PFN.y));                          \
        eem23##X = pack2(__expf(PFN.z), __expf(PFN.w));                          \
        PFN = *reinterpret_cast<const float4*>(emj4##X + (size_t)CL((S) + 3) * SSTR); \
    }

    // branch-free hot loop: steps 1..506 (all indices provably in-bounds)
    for (int k = 0; k < 253; k++) {
        const int s = 1 + (k << 1);
        CRF_STEP(A, 0, 1, s, pfEA, NOCL)
        CRF_STEP(B, 1, 1, s, pfEB, NOCL)
        __syncwarp();
        CRF_STEP(A, 0, 0, s + 1, pfOA, NOCL)
        CRF_STEP(B, 1, 0, s + 1, pfOB, NOCL)
        __syncwarp();
    }
    // peeled tail: steps 507..511 with clamped prefetch indices
    CRF_STEP(A, 0, 1, 507, pfEA, CLV)  CRF_STEP(B, 1, 1, 507, pfEB, CLV)
    __syncwarp();
    CRF_STEP(A, 0, 0, 508, pfOA, CLV)  CRF_STEP(B, 1, 0, 508, pfOB, CLV)
    __syncwarp();
    CRF_STEP(A, 0, 1, 509, pfEA, CLV)  CRF_STEP(B, 1, 1, 509, pfEB, CLV)
    __syncwarp();
    CRF_STEP(A, 0, 0, 510, pfOA, CLV)  CRF_STEP(B, 1, 0, 510, pfOB, CLV)
    __syncwarp();
    CRF_STEP(A, 0, 1, 511, pfEA, CLV)  CRF_STEP(B, 1, 1, 511, pfEB, CLV)

#undef CRF_STEP
#undef CRF_INIT

    // ---------------- normalizers ----------------
#define CRF_FIN(X)                                                               \
    {                                                                            \
        float4 e4 = *reinterpret_cast<const float4*>(end_t + 4 * c);             \
        float y0, y1, y2, y3;                                                    \
        unpack2(y01##X, y0, y1); unpack2(y23##X, y2, y3);                        \
        float v = y0 * __expf(e4.x) + y1 * __expf(e4.y)                          \
                + y2 * __expf(e4.z) + y3 * __expf(e4.w);                         \
        _Pragma("unroll")                                                        \
        for (int off = 16; off; off >>= 1)                                       \
            v += __shfl_xor_sync(0xffffffffu, v, off);                           \
        v *= 0.5f;                                                               \
        if (lane == 0) g_partial[b##X] = sc##X - (Mtot##X + __logf(v));          \
    }

    CRF_FIN(A)
    CRF_FIN(B)
#undef CRF_FIN

    if (lane == 0) __threadfence();
    __syncwarp();

    // ---------------- merged deterministic final reduction (last block) ----------------
    int last = 0;
    if (lane == 0) {
        unsigned int old = atomicAdd(&g_ctr, 1);
        last = (old == (unsigned int)(gridDim.x - 1));
    }
    last = __shfl_sync(0xffffffffu, last, 0);
    if (last) {
        __threadfence();
        float s = 0.f;
#pragma unroll
        for (int i = 0; i < NB / 32; i++)
            s += g_partial[lane + i * 32];
#pragma unroll
        for (int off = 16; off; off >>= 1)
            s += __shfl_xor_sync(0xffffffffu, s, off);
        if (lane == 0) { out[0] = s; g_ctr = 0; }
    }
}

extern "C" void kernel_launch(void* const* d_in, const int* in_sizes, int n_in,
                              void* d_out, int out_size) {
    const float* em    = (const float*)d_in[0];
    const float* trans = (const float*)d_in[1];
    const float* st    = (const float*)d_in[2];
    const float* et    = (const float*)d_in[3];
    const int*   tags  = (const int*)d_in[4];
    const int*   mask  = (const int*)d_in[5];

    crf_kernel<<<NB / 2, 32>>>(em, trans, st, et, tags, mask, (float*)d_out);
}

// round 9
// speedup vs baseline: 1.2404x; 1.2404x over previous
#include <cuda_runtime.h>
#include <cstdint>
#include <cstddef>

#define NS 512
#define NB 1024
#define NT 64
#define QSTRIDE 68   // 32 u64 (q0..31) + 2 pad + 32 u64 (q32..63) + 2 pad

__device__ float g_partial[NB];
__device__ unsigned int g_ctr = 0;

typedef unsigned long long u64;

__device__ __forceinline__ u64 pack2(float lo, float hi) {
    u64 r; asm("mov.b64 %0, {%1, %2};" : "=l"(r) : "f"(lo), "f"(hi)); return r;
}
__device__ __forceinline__ void unpack2(u64 v, float& lo, float& hi) {
    asm("mov.b64 {%0, %1}, %2;" : "=f"(lo), "=f"(hi) : "l"(v));
}
__device__ __forceinline__ void fma2(u64& acc, u64 a, u64 b) {
    asm("fma.rn.f32x2 %0, %1, %2, %0;" : "+l"(acc) : "l"(a), "l"(b));
}
__device__ __forceinline__ u64 add2(u64 a, u64 b) {
    u64 r; asm("add.rn.f32x2 %0, %1, %2;" : "=l"(r) : "l"(a), "l"(b)); return r;
}
__device__ __forceinline__ u64 mul2(u64 a, u64 b) {
    u64 r; asm("mul.rn.f32x2 %0, %1, %2;" : "=l"(r) : "l"(a), "l"(b)); return r;
}
__device__ __forceinline__ float frcp(float x) {
    float r; asm("rcp.approx.f32 %0, %1;" : "=f"(r) : "f"(x)); return r;
}
__device__ __forceinline__ u64 shflx16_u64(u64 v) {
    unsigned lo = (unsigned)v, hi = (unsigned)(v >> 32);
    lo = __shfl_xor_sync(0xffffffffu, lo, 16);
    hi = __shfl_xor_sync(0xffffffffu, hi, 16);
    return ((u64)hi << 32) | lo;
}
__device__ __forceinline__ void sts128(u64* p, float a, float b, float c, float d) {
    asm volatile("st.shared.v4.f32 [%0], {%1, %2, %3, %4};"
                 :: "l"(p), "f"(a), "f"(b), "f"(c), "f"(d) : "memory");
}
__device__ __forceinline__ void cp_async8(void* smem_dst, const void* gsrc) {
    unsigned s = (unsigned)__cvta_generic_to_shared(smem_dst);
    asm volatile("cp.async.ca.shared.global [%0], [%1], 8;" :: "r"(s), "l"(gsrc));
}
#define CP_COMMIT() asm volatile("cp.async.commit_group;" ::: "memory")
#define CP_WAIT(n)  asm volatile("cp.async.wait_group %0;" :: "n"(n) : "memory")

__global__ void __launch_bounds__(32)
crf_kernel(const float* __restrict__ em,
           const float* __restrict__ trans,
           const float* __restrict__ start_t,
           const float* __restrict__ end_t,
           const int* __restrict__ tags,
           const int* __restrict__ mask,
           float* __restrict__ out) {
    __shared__ __align__(16) u64   qsm[2][QSTRIDE];
    __shared__ __align__(16) float emring[8][NT];

    const int lane = threadIdx.x;        // one warp = one chain
    const int b    = blockIdx.x;
    const int c    = lane & 15;          // owns cols 4c..4c+3
    const int h    = lane >> 4;          // row half
    const size_t SSTR = (size_t)NB * NT;

    // ---------------- numerator: gold-path score ----------------
    float sc = 0.f;
    {
        int msum = 0;
#pragma unroll
        for (int k = 0; k < 16; k++) {
            int s = 1 + lane + (k << 5);
            if (s < NS) {
                int tp = tags[(s - 1) * NB + b];
                int tc = tags[s * NB + b];
                int mv = mask[s * NB + b];
                float term = trans[tp * NT + tc] + em[((size_t)s * NB + b) * NT + tc];
                sc += term * (float)mv;
                msum += mv;
            }
        }
#pragma unroll
        for (int off = 16; off; off >>= 1) {
            sc   += __shfl_xor_sync(0xffffffffu, sc, off);
            msum += __shfl_xor_sync(0xffffffffu, msum, off);
        }
        int t0 = tags[b];
        sc += start_t[t0] + em[(size_t)b * NT + t0];
        int seq_end = mask[b] + msum - 1;
        int lt = tags[(size_t)seq_end * NB + b];
        sc += end_t[lt];
    }

    // ---------------- mask bitset: lane l holds bits for steps 16l..16l+15 ----------
    unsigned mbits = 0;
#pragma unroll
    for (int k = 0; k < 16; k++) {
        int s = 16 * lane + k;
        mbits |= (unsigned)(mask[s * NB + b] & 1) << k;
    }

    // ---------------- start cp.async em pipeline: slots for steps 1..8 ----------------
#pragma unroll
    for (int t = 1; t <= 8; t++) {
        cp_async8(&emring[t & 7][2 * lane], em + ((size_t)t * NB + b) * NT + 2 * lane);
        CP_COMMIT();
    }

    // ---------------- E = exp(trans): my 32 rows x my 4 cols ----------------
    u64 EA[32], EB[32];
#pragma unroll
    for (int i = 0; i < 32; i++) {
        float4 t4 = *reinterpret_cast<const float4*>(trans + (32 * h + i) * NT + 4 * c);
        EA[i] = pack2(__expf(t4.x), __expf(t4.y));
        EB[i] = pack2(__expf(t4.z), __expf(t4.w));
    }

    // ---------------- init recursion state (symmetric) ----------------
    const int sidx = 4 * c + ((c >= 8) ? 2 : 0);
    u64 y01, y23;
    {
        const float* emj4 = em + (size_t)b * NT + 4 * c;
        float4 e0 = *reinterpret_cast<const float4*>(emj4);
        float4 s4 = *reinterpret_cast<const float4*>(start_t + 4 * c);
        y01 = pack2(__expf(s4.x + e0.x), __expf(s4.y + e0.y));
        y23 = pack2(__expf(s4.z + e0.z), __expf(s4.w + e0.w));
        float y0, y1, y2, y3;
        unpack2(y01, y0, y1); unpack2(y23, y2, y3);
        if (h == 0) {
            sts128(qsm[1] + sidx,     y0, y0, y1, y1);
            sts128(qsm[1] + sidx + 2, y2, y2, y3, y3);
        }
    }
    float rcur = 1.f, lpend = 0.f, Mtot = 0.f;   // replicated in every lane

    // eemCur = exp(em[1]) from ring slot 1
    u64 eem01, eem23;
    {
        CP_WAIT(7);
        __syncwarp();
        float4 e1 = *reinterpret_cast<const float4*>(&emring[1][4 * c]);
        eem01 = pack2(__expf(e1.x), __expf(e1.y));
        eem23 = pack2(__expf(e1.z), __expf(e1.w));
    }

    const float* emb2l = em + (size_t)b * NT + 2 * lane;   // cp.async source base

    // ---------------- branch-free forward recursion, steps 1..511 ----------------
    for (int s = 1; s < NS; s++) {
        CP_WAIT(6);          // em[s+1] resident
        __syncwarp();        // cross-lane visibility (also q STS->LDS ordering)

        const int p = s & 1;
        const u64* qh = qsm[p] + h * 34;
        u64 A0 = 0, A1 = 0, A2 = 0, A3 = 0;
        u64 B0 = 0, B1 = 0, B2 = 0, B3 = 0;
#pragma unroll
        for (int i = 0; i < 32; i += 4) {
            ulonglong2 q0 = *reinterpret_cast<const ulonglong2*>(qh + i);
            ulonglong2 q1 = *reinterpret_cast<const ulonglong2*>(qh + i + 2);
            fma2(A0, q0.x, EA[i]);     fma2(B0, q0.x, EB[i]);
            fma2(A1, q0.y, EA[i + 1]); fma2(B1, q0.y, EB[i + 1]);
            fma2(A2, q1.x, EA[i + 2]); fma2(B2, q1.x, EB[i + 2]);
            fma2(A3, q1.y, EA[i + 3]); fma2(B3, q1.y, EB[i + 3]);
        }
        u64 S01 = add2(add2(A0, A1), add2(A2, A3));
        u64 S23 = add2(add2(B0, B1), add2(B2, B3));
        S01 = add2(S01, shflx16_u64(S01));
        S23 = add2(S23, shflx16_u64(S23));
        float alo, ahi; unpack2(S01, alo, ahi);
        float a0raw = __shfl_sync(0xffffffffu, alo, 0);

        const int mk = (int)((__shfl_sync(0xffffffffu, mbits, s >> 4) >> (s & 15)) & 1u);

        u64 rp = pack2(rcur, rcur);
        u64 c01 = mul2(mul2(S01, rp), eem01);
        u64 c23 = mul2(mul2(S23, rp), eem23);
        if (mk) { y01 = c01; y23 = c23; }
        float y0, y1, y2, y3;
        unpack2(y01, y0, y1); unpack2(y23, y2, y3);
        u64* qn = qsm[p ^ 1];
        if (h == 0) {
            sts128(qn + sidx,     y0, y0, y1, y1);
            sts128(qn + sidx + 2, y2, y2, y3, y3);
        }
        float u0n = a0raw * rcur;
        if (mk) { Mtot += lpend; lpend = __logf(u0n); rcur = frcp(u0n); }

        // next eem from ring (em[s+1]); then refill slot with em[s+8]
        float4 en = *reinterpret_cast<const float4*>(&emring[(s + 1) & 7][4 * c]);
        eem01 = pack2(__expf(en.x), __expf(en.y));
        eem23 = pack2(__expf(en.z), __expf(en.w));
        int t = (s + 8 < NS) ? (s + 8) : (NS - 1);
        cp_async8(&emring[(s + 8) & 7][2 * lane], emb2l + (size_t)t * SSTR);
        CP_COMMIT();
    }

    // ---------------- normalizer = Mtot + lag-pending + log(sum_j y_j e^{end_j}) ------
    {
        float4 e4 = *reinterpret_cast<const float4*>(end_t + 4 * c);
        float y0, y1, y2, y3;
        unpack2(y01, y0, y1); unpack2(y23, y2, y3);
        float v = y0 * __expf(e4.x) + y1 * __expf(e4.y)
                + y2 * __expf(e4.z) + y3 * __expf(e4.w);
#pragma unroll
        for (int off = 16; off; off >>= 1)
            v += __shfl_xor_sync(0xffffffffu, v, off);
        v *= 0.5f;   // both halves contributed identical copies
        if (lane == 0) {
            g_partial[b] = sc - (Mtot + __logf(v));
            __threadfence();
        }
    }

    // ---------------- merged deterministic final reduction (last block) ----------------
    __syncwarp();
    int last = 0;
    if (lane == 0) {
        unsigned int old = atomicAdd(&g_ctr, 1);
        last = (old == (unsigned int)(gridDim.x - 1));
    }
    last = __shfl_sync(0xffffffffu, last, 0);
    if (last) {
        __threadfence();
        float s = 0.f;
#pragma unroll
        for (int i = 0; i < NB / 32; i++)
            s += g_partial[lane + i * 32];
#pragma unroll
        for (int off = 16; off; off >>= 1)
            s += __shfl_xor_sync(0xffffffffu, s, off);
        if (lane == 0) { out[0] = s; g_ctr = 0; }
    }
}

extern "C" void kernel_launch(void* const* d_in, const int* in_sizes, int n_in,
                              void* d_out, int out_size) {
    const float* em    = (const float*)d_in[0];
    const float* trans = (const float*)d_in[1];
    const float* st    = (const float*)d_in[2];
    const float* et    = (const float*)d_in[3];
    const int*   tags  = (const int*)d_in[4];
    const int*   mask  = (const int*)d_in[5];

    crf_kernel<<<NB, 32>>>(em, trans, st, et, tags, mask, (float*)d_out);
}